// round 8
// baseline (speedup 1.0000x reference)
#include <cuda_runtime.h>
#include <cuda_bf16.h>

// FilterLayer: y[b,c,h,w] = sum_{di,dj in 5x5} f[b, di*5+dj, h, w] * xpad[b, c, h+di, w+dj]
// x: [4,3,512,512] f32, f: [4,25,512,512] f32, out: [4,3,512,512] f32, zero pad p=2.
//
// R7: DRAM page-locality pass.
//  - Block covers the FULL 512-px row width (128 threads x 4px) x 2 rows.
//    Per filter plane a block reads 2 x 2KB fully-contiguous rows; consecutive
//    blocks (grid y-fastest) read adjacent row pairs of the same planes ->
//    the chip-wide read front is ~50 dense sequential streams, not scattered
//    512B chunks. This targets HBM row-buffer hit rate.
//  - f via __ldcs (evict-first: keeps the 12.6MB x tensor L2-resident).
//  - x default-cached (25x reuse via L1/L2); out via __stcs.
//  - 4 px/thread, 64-reg budget, no double buffer (proven neutral in R3).

#define WIN 5
#define CH 3

__global__ __launch_bounds__(256, 4)
void FilterLayer_4664334483556_kernel(const float* __restrict__ x,
                                      const float* __restrict__ f,
                                      float* __restrict__ out)
{
    const int H = 512, W = 512;
    const int tx = threadIdx.x;            // 0..127  -> column
    const int ty = threadIdx.y;            // 0..1    -> row within pair
    const int b  = blockIdx.z;
    const int h  = blockIdx.y * 2 + ty;    // output row
    const int wb = tx * 4;                 // first of 4 output cols (0..508)

    const bool leftOK  = (wb >= 4);
    const bool rightOK = (wb <= W - 8);

    float acc[CH][4];
    #pragma unroll
    for (int c = 0; c < CH; c++)
        #pragma unroll
        for (int q = 0; q < 4; q++)
            acc[c][q] = 0.0f;

    const size_t HW = (size_t)H * W;
    const float* fbase = f + ((size_t)b * (WIN * WIN)) * HW + (size_t)h * W + wb;
    const float* xbase = x + (size_t)b * CH * HW + wb;

    #pragma unroll
    for (int di = 0; di < WIN; di++) {
        const int gh = h + di - 2;
        const bool rv = ((unsigned)gh < (unsigned)H);

        // ---- filter row: 5 LDG.128, streaming (evict-first) ----
        float4 fv[WIN];
        #pragma unroll
        for (int dj = 0; dj < WIN; dj++)
            fv[dj] = __ldcs(reinterpret_cast<const float4*>(
                         fbase + (size_t)(di * WIN + dj) * HW));

        #pragma unroll
        for (int c = 0; c < CH; c++) {
            const float* row = xbase + ((size_t)c * H + gh) * W;

            float4 v0 = make_float4(0.f, 0.f, 0.f, 0.f);
            float4 v1 = make_float4(0.f, 0.f, 0.f, 0.f);
            float4 v2 = make_float4(0.f, 0.f, 0.f, 0.f);
            if (rv) {
                if (leftOK)  v0 = *reinterpret_cast<const float4*>(row - 4);
                             v1 = *reinterpret_cast<const float4*>(row);
                if (rightOK) v2 = *reinterpret_cast<const float4*>(row + 4);
            }

            float xr[8];
            xr[0] = v0.z; xr[1] = v0.w;
            xr[2] = v1.x; xr[3] = v1.y; xr[4] = v1.z; xr[5] = v1.w;
            xr[6] = v2.x; xr[7] = v2.y;

            #pragma unroll
            for (int dj = 0; dj < WIN; dj++) {
                acc[c][0] = fmaf(fv[dj].x, xr[dj + 0], acc[c][0]);
                acc[c][1] = fmaf(fv[dj].y, xr[dj + 1], acc[c][1]);
                acc[c][2] = fmaf(fv[dj].z, xr[dj + 2], acc[c][2]);
                acc[c][3] = fmaf(fv[dj].w, xr[dj + 3], acc[c][3]);
            }
        }
    }

    float* ob = out + (size_t)b * CH * HW + (size_t)h * W + wb;
    #pragma unroll
    for (int c = 0; c < CH; c++) {
        float4 v = make_float4(acc[c][0], acc[c][1], acc[c][2], acc[c][3]);
        __stcs(reinterpret_cast<float4*>(ob + c * HW), v);
    }
}

extern "C" void kernel_launch(void* const* d_in, const int* in_sizes, int n_in,
                              void* d_out, int out_size)
{
    const float* x = (const float*)d_in[0];
    const float* f = (const float*)d_in[1];
    float* out = (float*)d_out;

    dim3 block(128, 2, 1);       // full row width, 2 rows, 256 threads
    dim3 grid(1, 256, 4);        // 1024 blocks; y-fastest -> adjacent row pairs
    FilterLayer_4664334483556_kernel<<<grid, block>>>(x, f, out);
}

// round 9
// speedup vs baseline: 1.0439x; 1.0439x over previous
#include <cuda_runtime.h>
#include <cuda_bf16.h>
#include <cstdint>

// FilterLayer: y[b,c,h,w] = sum_{di,dj in 5x5} f[b, di*5+dj, h, w] * xpad[b, c, h+di, w+dj]
// x: [4,3,512,512] f32, f: [4,25,512,512] f32, out: [4,3,512,512] f32, zero pad p=2.
//
// R8: f stream moved off the warp-LSU path onto cp.async.bulk (UBLKCP, async
// proxy, mbarrier completion). 2-stage smem ring, one stage = one window row
// (5 planes x 4 tile rows x 512B = 10 KB). Consumers read fv via LDS.128
// (tx*16B -> conflict-free). x keeps the LDG/L1 path (25x reuse), out plain STG.

#define WIN 5
#define CH 3
#define TROWS 4          // tile rows per block
#define TCOLS 128        // tile cols per block
#define STAGE_BYTES (WIN * TROWS * TCOLS * 4)   // 10240

__device__ __forceinline__ uint32_t smem_u32(const void* p) {
    uint32_t a;
    asm("{ .reg .u64 t; cvta.to.shared.u64 t, %1; cvt.u32.u64 %0, t; }"
        : "=r"(a) : "l"(p));
    return a;
}

__device__ __forceinline__ void mbar_init(uint32_t mbar, uint32_t count) {
    asm volatile("mbarrier.init.shared.b64 [%0], %1;" :: "r"(mbar), "r"(count) : "memory");
}
__device__ __forceinline__ void mbar_expect_tx(uint32_t mbar, uint32_t bytes) {
    asm volatile("mbarrier.arrive.expect_tx.shared.b64 _, [%0], %1;"
                 :: "r"(mbar), "r"(bytes) : "memory");
}
__device__ __forceinline__ void mbar_wait(uint32_t mbar, uint32_t parity) {
    uint32_t done;
    asm volatile(
        "{\n\t.reg .pred p;\n\t"
        "mbarrier.try_wait.parity.acquire.cta.shared::cta.b64 p, [%1], %2;\n\t"
        "selp.b32 %0, 1, 0, p;\n\t}"
        : "=r"(done) : "r"(mbar), "r"(parity) : "memory");
    if (!done) {
        asm volatile(
            "{\n\t.reg .pred P1;\n\t"
            "W_%=:\n\t"
            "mbarrier.try_wait.parity.acquire.cta.shared::cta.b64 P1, [%0], %1, 0x989680;\n\t"
            "@P1 bra.uni D_%=;\n\t"
            "bra.uni W_%=;\n\t"
            "D_%=:\n\t}"
            :: "r"(mbar), "r"(parity) : "memory");
    }
}
__device__ __forceinline__ void bulk_copy_512(uint32_t dst_smem, const void* src, uint32_t mbar) {
    asm volatile(
        "cp.async.bulk.shared::cluster.global.mbarrier::complete_tx::bytes "
        "[%0], [%1], 512, [%2];"
        :: "r"(dst_smem), "l"(src), "r"(mbar) : "memory");
}

__global__ __launch_bounds__(128, 8)
void FilterLayer_4664334483556_kernel(const float* __restrict__ x,
                                      const float* __restrict__ f,
                                      float* __restrict__ out)
{
    __shared__ float sf[2][WIN][TROWS][TCOLS];             // 2 x 10 KB
    __shared__ __align__(8) unsigned long long mbar_s[2];

    const int H = 512, W = 512;
    const int tx = threadIdx.x;              // 0..31
    const int ty = threadIdx.y;              // 0..3
    const int tid = ty * 32 + tx;
    const int b  = blockIdx.z;
    const int h0 = blockIdx.y * TROWS;
    const int w0 = blockIdx.x * TCOLS;
    const int h  = h0 + ty;
    const int wb = w0 + tx * 4;

    const uint32_t mb0 = smem_u32(&mbar_s[0]);
    const uint32_t mb1 = smem_u32(&mbar_s[1]);
    const uint32_t sf0 = smem_u32(&sf[0][0][0][0]);

    const size_t HW = (size_t)H * W;
    const float* fblk = f + ((size_t)b * (WIN * WIN)) * HW + (size_t)h0 * W + w0;

    if (tid == 0) { mbar_init(mb0, 1); mbar_init(mb1, 1); }
    __syncthreads();

    // ---- producer: stage `di` into buffer `buf` (warp 0 only) ----
    auto issue_stage = [&](int di, int buf, uint32_t mb) {
        if (tid == 0) mbar_expect_tx(mb, STAGE_BYTES);
        __syncwarp();
        if (tid < WIN * TROWS) {                  // 20 copies of 512 B
            int dj = tid >> 2;
            int r  = tid & 3;
            const float* src = fblk + (size_t)(di * WIN + dj) * HW + (size_t)r * W;
            uint32_t dst = sf0 + (uint32_t)(buf * STAGE_BYTES
                                            + (dj * TROWS + r) * TCOLS * 4);
            bulk_copy_512(dst, src, mb);
        }
    };

    if (tid < 32) { issue_stage(0, 0, mb0); issue_stage(1, 1, mb1); }

    const bool leftOK  = (wb >= 4);
    const bool rightOK = (wb <= W - 8);

    float acc[CH][4];
    #pragma unroll
    for (int c = 0; c < CH; c++)
        #pragma unroll
        for (int q = 0; q < 4; q++)
            acc[c][q] = 0.0f;

    const float* xbase = x + (size_t)b * CH * HW + wb;

    #pragma unroll
    for (int di = 0; di < WIN; di++) {
        const int buf = di & 1;
        const uint32_t mb = buf ? mb1 : mb0;
        mbar_wait(mb, (di >> 1) & 1);

        // read this stage's filter vectors: 5 x LDS.128, conflict-free
        float4 fv[WIN];
        #pragma unroll
        for (int dj = 0; dj < WIN; dj++)
            fv[dj] = *reinterpret_cast<const float4*>(&sf[buf][dj][ty][tx * 4]);

        const int gh = h + di - 2;
        const bool rv = ((unsigned)gh < (unsigned)H);

        #pragma unroll
        for (int c = 0; c < CH; c++) {
            const float* row = xbase + ((size_t)c * H + gh) * W;
            float4 v0 = make_float4(0.f, 0.f, 0.f, 0.f);
            float4 v1 = make_float4(0.f, 0.f, 0.f, 0.f);
            float4 v2 = make_float4(0.f, 0.f, 0.f, 0.f);
            if (rv) {
                if (leftOK)  v0 = *reinterpret_cast<const float4*>(row - 4);
                             v1 = *reinterpret_cast<const float4*>(row);
                if (rightOK) v2 = *reinterpret_cast<const float4*>(row + 4);
            }
            float xr[8];
            xr[0] = v0.z; xr[1] = v0.w;
            xr[2] = v1.x; xr[3] = v1.y; xr[4] = v1.z; xr[5] = v1.w;
            xr[6] = v2.x; xr[7] = v2.y;

            #pragma unroll
            for (int dj = 0; dj < WIN; dj++) {
                acc[c][0] = fmaf(fv[dj].x, xr[dj + 0], acc[c][0]);
                acc[c][1] = fmaf(fv[dj].y, xr[dj + 1], acc[c][1]);
                acc[c][2] = fmaf(fv[dj].z, xr[dj + 2], acc[c][2]);
                acc[c][3] = fmaf(fv[dj].w, xr[dj + 3], acc[c][3]);
            }
        }

        __syncthreads();                      // all consumers done with buf
        if (di + 2 < WIN && tid < 32)
            issue_stage(di + 2, buf, mb);     // refill for di+2
    }

    float* ob = out + (size_t)b * CH * HW + (size_t)h * W + wb;
    #pragma unroll
    for (int c = 0; c < CH; c++) {
        float4 v = make_float4(acc[c][0], acc[c][1], acc[c][2], acc[c][3]);
        *reinterpret_cast<float4*>(ob + c * HW) = v;
    }
}

extern "C" void kernel_launch(void* const* d_in, const int* in_sizes, int n_in,
                              void* d_out, int out_size)
{
    const float* x = (const float*)d_in[0];
    const float* f = (const float*)d_in[1];
    float* out = (float*)d_out;

    dim3 block(32, 4, 1);
    dim3 grid(4, 128, 4);   // (512/128, 512/4, 4) = 2048 blocks
    FilterLayer_4664334483556_kernel<<<grid, block>>>(x, f, out);
}